// round 17
// baseline (speedup 1.0000x reference)
#include <cuda_runtime.h>
#include <cuda_fp16.h>

// warp3D: out[b,c,z,y,x] = trilinear gather of I at (x+fx, y+fy, z+fz)
// B=2, C=2, D=160, H=192, W=224, fp32 in/out.
//
// R17: overlap pack and gather via z-chunking + two streams.
//   pack chunks run on stream s2 (event per chunk); main chunk c on the
//   origin stream waits ev[c+1] => z < 20*(c+2) is packed. Rare voxels
//   whose z1 exceeds the packed frontier take an exact fp32 raw-I
//   fallback. Layouts/tuning frozen from R16:
//   It = half2(c0,c1) 4B/voxel (55 MB, L2-resident); main VPT=4,
//   __launch_bounds__(224,5), __ldcs flow, __stcs out.

#define Wd 224
#define Hd 192
#define Dd 160
#define Bd 2
#define HWd (Hd * Wd)            // 43008
#define DHWd (Dd * HWd)          // 6881280
#define VPT 4                    // voxels per thread (along y)
#define NCH 8                    // z chunks
#define ZCH (Dd / NCH)           // 20

__device__ __forceinline__ unsigned int h2_to_u(__half2 h) {
    return *reinterpret_cast<unsigned int*>(&h);
}
__device__ __forceinline__ __half2 u_to_h2(unsigned int u) {
    return *reinterpret_cast<__half2*>(&u);
}

// 13.76M voxels * 4B = 55 MB scratch (L2-resident)
__device__ unsigned int g_It[(long)Bd * DHWd];

// Pack one z-chunk: thread = x-quad: 2 x LDG.128 -> 1 x STG.128.
__global__ __launch_bounds__(224) void pack_kernel(const float* __restrict__ I,
                                                   int zbase)
{
    const int q = threadIdx.x;                 // 0..55
    const int y = blockIdx.x * 4 + threadIdx.y;
    const int z = zbase + blockIdx.y;
    const int b = blockIdx.z;

    const int x = 4 * q;
    const int s = z * HWd + y * Wd + x;        // 16B aligned
    const float* __restrict__ I0 = I + (long)b * 2 * DHWd;
    const float* __restrict__ I1 = I0 + DHWd;

    const float4 a = __ldg((const float4*)(I0 + s));
    const float4 c = __ldg((const float4*)(I1 + s));

    uint4 v;
    v.x = h2_to_u(__floats2half2_rn(a.x, c.x));
    v.y = h2_to_u(__floats2half2_rn(a.y, c.y));
    v.z = h2_to_u(__floats2half2_rn(a.z, c.z));
    v.w = h2_to_u(__floats2half2_rn(a.w, c.w));
    *reinterpret_cast<uint4*>(g_It + (long)b * DHWd + s) = v;
}

// Gather one z-chunk. zlim = first z NOT yet guaranteed packed.
__global__ __launch_bounds__(Wd, 5) void warp3d_kernel(
    const float* __restrict__ I,
    const float* __restrict__ flow,
    float* __restrict__ out,
    int zbase, int zlim)
{
    const int x  = threadIdx.x;          // 0..223
    const int yb = blockIdx.x * VPT;
    const int z  = zbase + blockIdx.y;
    const int b  = blockIdx.z;

    const float* __restrict__ fb = flow + (long)b * 3 * DHWd;
    const unsigned int* __restrict__ Ic = g_It + (long)b * DHWd;
    const float* __restrict__ I0 = I + (long)b * 2 * DHWd;
    const float* __restrict__ I1 = I0 + DHWd;
    float* __restrict__ ob = out + (long)b * 2 * DHWd;

    const int s0 = z * HWd + yb * Wd + x;

    // ---- Stage A: all flow loads in flight (12 LDG.32, evict-first) ----
    float fxv[VPT], fyv[VPT], fzv[VPT];
#pragma unroll
    for (int v = 0; v < VPT; ++v) {
        const int s = s0 + v * Wd;
        fxv[v] = __ldcs(fb + s);
        fyv[v] = __ldcs(fb + s + DHWd);
        fzv[v] = __ldcs(fb + s + 2L * DHWd);
    }

    // ---- Stage B: coords + gathers ----
    float w00[VPT], w10[VPT], w01[VPT], w11[VPT], dzv[VPT], ezv[VPT];
    unsigned int a00[VPT], a01[VPT], a10[VPT], a11[VPT];
    unsigned int c00[VPT], c01[VPT], c10[VPT], c11[VPT];
    int rx00[VPT], rx01[VPT], rx10[VPT], rx11[VPT];  // row bases (for fallback)
    int xx0[VPT], xx1[VPT];
    bool fb_raw[VPT];

#pragma unroll
    for (int v = 0; v < VPT; ++v) {
        const int y = yb + v;
        const float xf = fxv[v] + (float)x;
        const float yf = fyv[v] + (float)y;
        const float zf = fzv[v] + (float)z;

        int x0 = (int)floorf(xf);
        int y0 = (int)floorf(yf);
        int z0 = (int)floorf(zf);
        // upper corner from UNclamped lower+1, then clamp (matches ref)
        const int x1 = min(max(x0 + 1, 0), Wd - 1);
        const int y1 = min(max(y0 + 1, 0), Hd - 1);
        const int z1 = min(max(z0 + 1, 0), Dd - 1);
        x0 = min(max(x0, 0), Wd - 1);
        y0 = min(max(y0, 0), Hd - 1);
        z0 = min(max(z0, 0), Dd - 1);

        const float dx = (float)x1 - xf;
        const float dy = (float)y1 - yf;
        const float dz = (float)z1 - zf;
        const float ex = 1.0f - dx;
        const float ey = 1.0f - dy;

        w00[v] = dx * dy;
        w01[v] = ex * dy;
        w10[v] = dx * ey;
        w11[v] = ex * ey;
        dzv[v] = dz;
        ezv[v] = 1.0f - dz;

        const int r00 = z0 * HWd + y0 * Wd;
        const int r10 = z0 * HWd + y1 * Wd;
        const int r01 = z1 * HWd + y0 * Wd;
        const int r11 = z1 * HWd + y1 * Wd;
        rx00[v] = r00; rx10[v] = r10; rx01[v] = r01; rx11[v] = r11;
        xx0[v] = x0; xx1[v] = x1;

        // z1 >= zlim => that slab may not be packed yet: raw-I fallback.
        fb_raw[v] = (z1 >= zlim);

        if (!fb_raw[v]) {
            a00[v] = __ldg(Ic + r00 + x0);
            a01[v] = __ldg(Ic + r00 + x1);
            a10[v] = __ldg(Ic + r10 + x0);
            a11[v] = __ldg(Ic + r10 + x1);
            c00[v] = __ldg(Ic + r01 + x0);
            c01[v] = __ldg(Ic + r01 + x1);
            c10[v] = __ldg(Ic + r11 + x0);
            c11[v] = __ldg(Ic + r11 + x1);
        }
    }

    // ---- Stage C: convert, reduce, store ----
#pragma unroll
    for (int v = 0; v < VPT; ++v) {
        float p0c0, p0c1, p1c0, p1c1;
        if (!fb_raw[v]) {
            const float2 f00 = __half22float2(u_to_h2(a00[v]));
            const float2 f01 = __half22float2(u_to_h2(a01[v]));
            const float2 f10 = __half22float2(u_to_h2(a10[v]));
            const float2 f11 = __half22float2(u_to_h2(a11[v]));
            const float2 g00 = __half22float2(u_to_h2(c00[v]));
            const float2 g01 = __half22float2(u_to_h2(c01[v]));
            const float2 g10 = __half22float2(u_to_h2(c10[v]));
            const float2 g11 = __half22float2(u_to_h2(c11[v]));
            p0c0 = w00[v]*f00.x + w01[v]*f01.x + w10[v]*f10.x + w11[v]*f11.x;
            p0c1 = w00[v]*f00.y + w01[v]*f01.y + w10[v]*f10.y + w11[v]*f11.y;
            p1c0 = w00[v]*g00.x + w01[v]*g01.x + w10[v]*g10.x + w11[v]*g11.x;
            p1c1 = w00[v]*g00.y + w01[v]*g01.y + w10[v]*g10.y + w11[v]*g11.y;
        } else {
            // Exact fp32 trilinear straight from I (rare).
            const int r00 = rx00[v], r10 = rx10[v], r01 = rx01[v], r11 = rx11[v];
            const int x0 = xx0[v], x1 = xx1[v];
            p0c0 = w00[v]*__ldg(I0+r00+x0) + w01[v]*__ldg(I0+r00+x1)
                 + w10[v]*__ldg(I0+r10+x0) + w11[v]*__ldg(I0+r10+x1);
            p0c1 = w00[v]*__ldg(I1+r00+x0) + w01[v]*__ldg(I1+r00+x1)
                 + w10[v]*__ldg(I1+r10+x0) + w11[v]*__ldg(I1+r10+x1);
            p1c0 = w00[v]*__ldg(I0+r01+x0) + w01[v]*__ldg(I0+r01+x1)
                 + w10[v]*__ldg(I0+r11+x0) + w11[v]*__ldg(I0+r11+x1);
            p1c1 = w00[v]*__ldg(I1+r01+x0) + w01[v]*__ldg(I1+r01+x1)
                 + w10[v]*__ldg(I1+r11+x0) + w11[v]*__ldg(I1+r11+x1);
        }

        const int s = s0 + v * Wd;
        __stcs(ob + s,        dzv[v] * p0c0 + ezv[v] * p1c0);
        __stcs(ob + s + DHWd, dzv[v] * p0c1 + ezv[v] * p1c1);
    }
}

extern "C" void kernel_launch(void* const* d_in, const int* in_sizes, int n_in,
                              void* d_out, int out_size)
{
    const float* I    = (const float*)d_in[0];
    const float* flow = (const float*)d_in[1];
    float* out        = (float*)d_out;

    // Streams/events created once, on the first (uncaptured) call.
    static cudaStream_t s2 = nullptr;
    static cudaEvent_t ev[NCH];
    if (!s2) {
        cudaStreamCreateWithFlags(&s2, cudaStreamNonBlocking);
        for (int c = 0; c < NCH; ++c)
            cudaEventCreateWithFlags(&ev[c], cudaEventDisableTiming);
    }

    // Fork s2 off the origin stream so capture sees the dependency.
    static cudaEvent_t fork_ev = nullptr;
    if (!fork_ev) cudaEventCreateWithFlags(&fork_ev, cudaEventDisableTiming);
    cudaEventRecord(fork_ev, 0);
    cudaStreamWaitEvent(s2, fork_ev, 0);

    dim3 pblock(56, 4, 1);                    // 224 thr
    dim3 pgrid(Hd / 4, ZCH, Bd);              // 48 x 20 x 2 per chunk
    for (int c = 0; c < NCH; ++c) {
        pack_kernel<<<pgrid, pblock, 0, s2>>>(I, c * ZCH);
        cudaEventRecord(ev[c], s2);
    }

    dim3 block(Wd, 1, 1);                     // 224 thr
    dim3 grid(Hd / VPT, ZCH, Bd);             // 48 x 20 x 2 per chunk
    for (int c = 0; c < NCH; ++c) {
        const int need = min(c + 1, NCH - 1); // chunks 0..need are packed
        cudaStreamWaitEvent(0, ev[need], 0);
        const int zlim = (need + 1) * ZCH;    // z < zlim guaranteed packed
        warp3d_kernel<<<grid, block>>>(I, flow, out, c * ZCH, zlim);
    }
}